// round 9
// baseline (speedup 1.0000x reference)
#include <cuda_runtime.h>
#include <cuda_bf16.h>

// R6: row-packed f32x2 math. The two rows processed per iteration live in the
// lo/hi lanes of 64-bit packed registers; the 110 scalar Horner FMAs per
// iteration become 55 FFMA2 (fma.rn.f32x2 - PTX-only on sm_103a). Coefficients
// are register-resident duplicated pairs. 128-thread blocks, 3 CTAs/SM.

#define NBLK 444              // 148 SMs * 3 CTAs
#define NTHR 128
#define TOTT (NBLK * NTHR)    // 56832 threads, 113664 rows/iter

typedef unsigned long long u64;

__device__ __forceinline__ u64 pk2(float lo, float hi) {
    u64 p;
    asm("mov.b64 %0, {%1, %2};" : "=l"(p)
        : "r"(__float_as_uint(lo)), "r"(__float_as_uint(hi)));
    return p;
}
__device__ __forceinline__ void upk2(u64 p, float& lo, float& hi) {
    unsigned int a, b;
    asm("mov.b64 {%0, %1}, %2;" : "=r"(a), "=r"(b) : "l"(p));
    lo = __uint_as_float(a);
    hi = __uint_as_float(b);
}
__device__ __forceinline__ u64 ffma2(u64 a, u64 b, u64 c) {
    u64 d;
    asm("fma.rn.f32x2 %0, %1, %2, %3;" : "=l"(d) : "l"(a), "l"(b), "l"(c));
    return d;
}
__device__ __forceinline__ u64 fmul2(u64 a, u64 b) {
    u64 d;
    asm("mul.rn.f32x2 %0, %1, %2;" : "=l"(d) : "l"(a), "l"(b));
    return d;
}
__device__ __forceinline__ u64 fadd2(u64 a, u64 b) {
    u64 d;
    asm("add.rn.f32x2 %0, %1, %2;" : "=l"(d) : "l"(a), "l"(b));
    return d;
}

template<int NITER>
__global__ __launch_bounds__(NTHR, 3)
void ExternalForcesSI_main_kernel(const float4* __restrict__ x,
                                  const float* __restrict__ t,
                                  const float* __restrict__ layer,
                                  const float* __restrict__ omegas,
                                  const float* __restrict__ ef,
                                  const int*   __restrict__ E,
                                  float2* __restrict__ out,
                                  int n, int iters_rt) {
    __shared__ float sC1[5];
    __shared__ float sC2[25];
    __shared__ float sC3[125];
    __shared__ float sTrig[10];

    // ---- block-local decode of E -> canonical coefficient slots ----
    const int tx = threadIdx.x;
    if (tx < 55) {
        int vars[3];
        int nv = 0;
        #pragma unroll
        for (int j = 0; j < 5; j++) {
            int c = E[tx * 5 + j];
            for (int r = 0; r < c; r++) vars[nv++] = j;   // ascending
        }
        float coef = layer[tx];
        if (nv == 1)      sC1[vars[0]] = coef;
        else if (nv == 2) sC2[vars[0] * 5 + vars[1]] = coef;
        else              sC3[(vars[0] * 5 + vars[1]) * 5 + vars[2]] = coef;
    }
    if (tx >= 64 && tx < 74) sTrig[tx - 64] = layer[55 + (tx - 64)];
    __syncthreads();

    // ---- coefficients as packed duplicated pairs, register-resident ----
    u64 c1p[5], c2p[15], c3p[35];
    float ctc[5], cts[5];
    {
        int q2 = 0, q3 = 0;
        #pragma unroll
        for (int i = 0; i < 5; i++) {
            float a = sC1[i];
            c1p[i] = pk2(a, a);
            ctc[i] = sTrig[i];
            cts[i] = sTrig[5 + i];
            #pragma unroll
            for (int j = i; j < 5; j++) {
                float b = sC2[i * 5 + j];
                c2p[q2++] = pk2(b, b);
                #pragma unroll
                for (int k = j; k < 5; k++) {
                    float c = sC3[(i * 5 + j) * 5 + k];
                    c3p[q3++] = pk2(c, c);
                }
            }
        }
    }
    const float w0 = omegas[0];
    const float w1 = omegas[1];
    const float e0 = ef[0];
    const float e1 = ef[1];

    const int tid = blockIdx.x * NTHR + tx;
    const int nm1 = n - 1;
    const int iters = (NITER > 0) ? NITER : iters_rt;

    // ---- prologue: clamped loads of first row pair (scalar regs) ----
    float va[5], vb[5];
    {
        int c0 = min(tid, nm1);
        int c1i = min(tid + TOTT, nm1);
        float4 x0 = x[c0];
        float4 x1 = x[c1i];
        float  t0 = t[c0];
        float  t1 = t[c1i];
        va[0] = x0.x; va[1] = x0.y; va[2] = x0.z; va[3] = x0.w; va[4] = t0;
        vb[0] = x1.x; vb[1] = x1.y; vb[2] = x1.z; vb[3] = x1.w; vb[4] = t1;
    }

    #pragma unroll
    for (int it = 0; it < iters; it++) {
        const int i0 = tid + it * (2 * TOTT);

        // ---- prefetch next row pair FIRST ----
        float na[5], nb[5];
        if (it + 1 < iters) {
            int c0 = min(i0 + 2 * TOTT, nm1);
            int c1i = min(i0 + 3 * TOTT, nm1);
            float4 x0 = x[c0];
            float4 x1 = x[c1i];
            float  t0 = t[c0];
            float  t1 = t[c1i];
            na[0] = x0.x; na[1] = x0.y; na[2] = x0.z; na[3] = x0.w; na[4] = t0;
            nb[0] = x1.x; nb[1] = x1.y; nb[2] = x1.z; nb[3] = x1.w; nb[4] = t1;
        }

        // ---- trig: issue all 20 MUFUs early (scalar) ----
        float Ca[5], Sa[5], Cb[5], Sb[5];
        #pragma unroll
        for (int j = 0; j < 5; j++) {
            Ca[j] = __cosf(w0 * va[j]);
            Sa[j] = __sinf(w1 * va[j]);
            Cb[j] = __cosf(w0 * vb[j]);
            Sb[j] = __sinf(w1 * vb[j]);
        }

        // ---- pack row pair for the polynomial ----
        u64 vp[5];
        #pragma unroll
        for (int j = 0; j < 5; j++) vp[j] = pk2(va[j], vb[j]);

        // ---- degree-3 Horner: 55 FFMA2 evaluate BOTH rows ----
        u64 acc;
        {
            int q2 = 0, q3 = 0;
            u64 parts[5];
            #pragma unroll
            for (int i = 0; i < 5; i++) {
                u64 ui = c1p[i];
                #pragma unroll
                for (int j = i; j < 5; j++) {
                    u64 tij = c2p[q2++];
                    #pragma unroll
                    for (int k = j; k < 5; k++)
                        tij = ffma2(vp[k], c3p[q3++], tij);
                    ui = ffma2(vp[j], tij, ui);
                }
                parts[i] = fmul2(vp[i], ui);
            }
            acc = fadd2(fadd2(fadd2(parts[0], parts[1]),
                              fadd2(parts[2], parts[3])), parts[4]);
        }

        // ---- trig accumulation (scalar trees) + epilogue ----
        float pa, pb;
        upk2(acc, pa, pb);
        {
            float a01 = fmaf(ctc[0], Ca[0], ctc[1] * Ca[1]);
            float a23 = fmaf(ctc[2], Ca[2], ctc[3] * Ca[3]);
            float b01 = fmaf(cts[0], Sa[0], cts[1] * Sa[1]);
            float b23 = fmaf(cts[2], Sa[2], cts[3] * Sa[3]);
            float a4  = fmaf(ctc[4], Ca[4], cts[4] * Sa[4]);
            float s   = pa + (((a01 + a23) + (b01 + b23)) + a4);
            if (i0 < n) out[i0] = make_float2(s * e0, s * e1);
        }
        {
            float a01 = fmaf(ctc[0], Cb[0], ctc[1] * Cb[1]);
            float a23 = fmaf(ctc[2], Cb[2], ctc[3] * Cb[3]);
            float b01 = fmaf(cts[0], Sb[0], cts[1] * Sb[1]);
            float b23 = fmaf(cts[2], Sb[2], cts[3] * Sb[3]);
            float a4  = fmaf(ctc[4], Cb[4], cts[4] * Sb[4]);
            float s   = pb + (((a01 + a23) + (b01 + b23)) + a4);
            int idx = i0 + TOTT;
            if (idx < n) out[idx] = make_float2(s * e0, s * e1);
        }

        // ---- rotate pipeline (renamed by the unroll) ----
        if (it + 1 < iters) {
            #pragma unroll
            for (int j = 0; j < 5; j++) { va[j] = na[j]; vb[j] = nb[j]; }
        }
    }
}

extern "C" void kernel_launch(void* const* d_in, const int* in_sizes, int n_in,
                              void* d_out, int out_size) {
    // metadata order: x, t, layer, omegas, ext_filter, E
    const float4* x      = (const float4*)d_in[0];
    const float*  t      = (const float*)d_in[1];
    const float*  layer  = (const float*)d_in[2];
    const float*  omegas = (const float*)d_in[3];
    const float*  ef     = (const float*)d_in[4];
    const int*    E      = (const int*)d_in[5];
    float2* out = (float2*)d_out;

    const int n = in_sizes[1];  // N_DATA (element count of t)
    const int iters = (n + 2 * TOTT - 1) / (2 * TOTT);

    if (iters == 9) {
        // N_DATA = 1M path: exact compile-time trip count, fully unrolled.
        ExternalForcesSI_main_kernel<9><<<NBLK, NTHR>>>(
            x, t, layer, omegas, ef, E, out, n, iters);
    } else {
        ExternalForcesSI_main_kernel<0><<<NBLK, NTHR>>>(
            x, t, layer, omegas, ef, E, out, n, iters);
    }
}

// round 10
// speedup vs baseline: 1.0392x; 1.0392x over previous
#include <cuda_runtime.h>
#include <cuda_bf16.h>

// R7 = R5 + adjacent-row pairing. Each thread handles rows (2p, 2p+1) which
// share one pair index:  t -> one float2 load, out -> ONE float4 store,
// x -> two adjacent float4 loads (same/adjacent 128B sector). Mem ops per
// 2-row iteration drop 6 -> 4 and index/clamp math halves. Coefficients stay
// register-resident (R4 proved LDS-in-loop loses; R6 proved packing loses).

#define NBLK 296
#define NTHR 256
#define TOTT (NBLK * NTHR)   // 75776 threads = 75776 row-pairs per iteration

template<int NITER>
__global__ __launch_bounds__(NTHR, 2)
void ExternalForcesSI_main_kernel(const float4* __restrict__ x,
                                  const float2* __restrict__ t2,
                                  const float* __restrict__ layer,
                                  const float* __restrict__ omegas,
                                  const float* __restrict__ ef,
                                  const int*   __restrict__ E,
                                  float4* __restrict__ out,
                                  int npairs, int iters_rt) {
    __shared__ float sC1[5];
    __shared__ float sC2[25];
    __shared__ float sC3[125];
    __shared__ float sTrig[10];

    // ---- block-local decode of E -> canonical coefficient slots ----
    const int tx = threadIdx.x;
    if (tx < 55) {
        int vars[3];
        int nv = 0;
        #pragma unroll
        for (int j = 0; j < 5; j++) {
            int c = E[tx * 5 + j];
            for (int r = 0; r < c; r++) vars[nv++] = j;   // ascending
        }
        float coef = layer[tx];
        if (nv == 1)      sC1[vars[0]] = coef;
        else if (nv == 2) sC2[vars[0] * 5 + vars[1]] = coef;
        else              sC3[(vars[0] * 5 + vars[1]) * 5 + vars[2]] = coef;
    }
    if (tx >= 64 && tx < 74) sTrig[tx - 64] = layer[55 + (tx - 64)];
    __syncthreads();

    // ---- hoist ALL coefficients into registers (broadcast LDS, once) ----
    float c1[5], c2[15], c3[35], ctc[5], cts[5];
    {
        int q2 = 0, q3 = 0;
        #pragma unroll
        for (int i = 0; i < 5; i++) {
            c1[i] = sC1[i];
            ctc[i] = sTrig[i];
            cts[i] = sTrig[5 + i];
            #pragma unroll
            for (int j = i; j < 5; j++) {
                c2[q2++] = sC2[i * 5 + j];
                #pragma unroll
                for (int k = j; k < 5; k++)
                    c3[q3++] = sC3[(i * 5 + j) * 5 + k];
            }
        }
    }
    const float w0 = omegas[0];
    const float w1 = omegas[1];
    const float e0 = ef[0];
    const float e1 = ef[1];

    const int tid = blockIdx.x * NTHR + tx;
    const int pm1 = npairs - 1;
    const int iters = (NITER > 0) ? NITER : iters_rt;

    // ---- prologue: clamped load of first row pair (3 LDGs) ----
    float va[5], vb[5];
    {
        int pc = min(tid, pm1);
        float4 x0 = x[2 * pc];
        float4 x1 = x[2 * pc + 1];
        float2 tt = t2[pc];
        va[0] = x0.x; va[1] = x0.y; va[2] = x0.z; va[3] = x0.w; va[4] = tt.x;
        vb[0] = x1.x; vb[1] = x1.y; vb[2] = x1.z; vb[3] = x1.w; vb[4] = tt.y;
    }

    #pragma unroll
    for (int it = 0; it < iters; it++) {
        const int p = tid + it * TOTT;

        // ---- prefetch next pair FIRST (LDGs in flight during compute) ----
        float na[5], nb[5];
        if (it + 1 < iters) {
            int pc = min(p + TOTT, pm1);
            float4 x0 = x[2 * pc];
            float4 x1 = x[2 * pc + 1];
            float2 tt = t2[pc];
            na[0] = x0.x; na[1] = x0.y; na[2] = x0.z; na[3] = x0.w; na[4] = tt.x;
            nb[0] = x1.x; nb[1] = x1.y; nb[2] = x1.z; nb[3] = x1.w; nb[4] = tt.y;
        }

        // ---- trig: issue all 20 MUFUs early ----
        float Ca[5], Sa[5], Cb[5], Sb[5];
        #pragma unroll
        for (int j = 0; j < 5; j++) {
            Ca[j] = __cosf(w0 * va[j]);
            Sa[j] = __sinf(w1 * va[j]);
            Cb[j] = __cosf(w0 * vb[j]);
            Sb[j] = __sinf(w1 * vb[j]);
        }

        // ---- degree-3 Horner: 55 FMAs/row, 5 independent ui chains ----
        float sA, sB;
        {
            float part[5];
            int q2 = 0, q3 = 0;
            #pragma unroll
            for (int i = 0; i < 5; i++) {
                float ui = c1[i];
                #pragma unroll
                for (int j = i; j < 5; j++) {
                    float tij = c2[q2++];
                    #pragma unroll
                    for (int k = j; k < 5; k++)
                        tij = fmaf(va[k], c3[q3++], tij);
                    ui = fmaf(va[j], tij, ui);
                }
                part[i] = va[i] * ui;
            }
            float a01 = fmaf(ctc[0], Ca[0], ctc[1] * Ca[1]);
            float a23 = fmaf(ctc[2], Ca[2], ctc[3] * Ca[3]);
            float b01 = fmaf(cts[0], Sa[0], cts[1] * Sa[1]);
            float b23 = fmaf(cts[2], Sa[2], cts[3] * Sa[3]);
            float a4  = fmaf(ctc[4], Ca[4], cts[4] * Sa[4]);
            sA = (((part[0] + part[1]) + (part[2] + part[3])) + part[4])
                 + (((a01 + a23) + (b01 + b23)) + a4);
        }
        {
            float part[5];
            int q2 = 0, q3 = 0;
            #pragma unroll
            for (int i = 0; i < 5; i++) {
                float ui = c1[i];
                #pragma unroll
                for (int j = i; j < 5; j++) {
                    float tij = c2[q2++];
                    #pragma unroll
                    for (int k = j; k < 5; k++)
                        tij = fmaf(vb[k], c3[q3++], tij);
                    ui = fmaf(vb[j], tij, ui);
                }
                part[i] = vb[i] * ui;
            }
            float a01 = fmaf(ctc[0], Cb[0], ctc[1] * Cb[1]);
            float a23 = fmaf(ctc[2], Cb[2], ctc[3] * Cb[3]);
            float b01 = fmaf(cts[0], Sb[0], cts[1] * Sb[1]);
            float b23 = fmaf(cts[2], Sb[2], cts[3] * Sb[3]);
            float a4  = fmaf(ctc[4], Cb[4], cts[4] * Sb[4]);
            sB = (((part[0] + part[1]) + (part[2] + part[3])) + part[4])
                 + (((a01 + a23) + (b01 + b23)) + a4);
        }

        // ---- ONE float4 store covers both rows ----
        if (p < npairs)
            out[p] = make_float4(sA * e0, sA * e1, sB * e0, sB * e1);

        // ---- rotate pipeline (renamed by the unroll) ----
        if (it + 1 < iters) {
            #pragma unroll
            for (int j = 0; j < 5; j++) { va[j] = na[j]; vb[j] = nb[j]; }
        }
    }
}

extern "C" void kernel_launch(void* const* d_in, const int* in_sizes, int n_in,
                              void* d_out, int out_size) {
    // metadata order: x, t, layer, omegas, ext_filter, E
    const float4* x      = (const float4*)d_in[0];
    const float2* t2     = (const float2*)d_in[1];
    const float*  layer  = (const float*)d_in[2];
    const float*  omegas = (const float*)d_in[3];
    const float*  ef     = (const float*)d_in[4];
    const int*    E      = (const int*)d_in[5];
    float4* out = (float4*)d_out;

    const int n = in_sizes[1];        // N_DATA (element count of t), even
    const int npairs = n >> 1;        // 500000
    const int iters = (npairs + TOTT - 1) / TOTT;

    if (iters == 7) {
        // N_DATA = 1M path: exact compile-time trip count, fully unrolled.
        ExternalForcesSI_main_kernel<7><<<NBLK, NTHR>>>(
            x, t2, layer, omegas, ef, E, out, npairs, iters);
    } else {
        ExternalForcesSI_main_kernel<0><<<NBLK, NTHR>>>(
            x, t2, layer, omegas, ef, E, out, npairs, iters);
    }
}

// round 11
// speedup vs baseline: 1.1536x; 1.1101x over previous
#include <cuda_runtime.h>
#include <cuda_bf16.h>

// R8 = R7 + instruction-overhead surgery:
//  - parity double-buffer (buf[it&1]) under full unroll -> rotation MOVs
//    become register renaming, zero copies
//  - guard specialization: iterations 0..5 provably in-bounds (75776*6+75775
//    < 500000 pairs) -> raw immediate-offset loads, unpredicated STG.128;
//    only the last iteration clamps/predicates
//  - single pointer-base per stream; per-iter offsets are unroll constants

#define NBLK 296
#define NTHR 256
#define TOTT (NBLK * NTHR)   // 75776 threads = 75776 row-pairs per iteration

struct Pair { float a[5]; float b[5]; };

__device__ __forceinline__ void load_pair(const float4* __restrict__ xp,
                                          const float2* __restrict__ tp,
                                          int off, Pair& P) {
    float4 x0 = xp[2 * off];
    float4 x1 = xp[2 * off + 1];
    float2 tt = tp[off];
    P.a[0] = x0.x; P.a[1] = x0.y; P.a[2] = x0.z; P.a[3] = x0.w; P.a[4] = tt.x;
    P.b[0] = x1.x; P.b[1] = x1.y; P.b[2] = x1.z; P.b[3] = x1.w; P.b[4] = tt.y;
}

template<int NITER>
__global__ __launch_bounds__(NTHR, 2)
void ExternalForcesSI_main_kernel(const float4* __restrict__ x,
                                  const float2* __restrict__ t2,
                                  const float* __restrict__ layer,
                                  const float* __restrict__ omegas,
                                  const float* __restrict__ ef,
                                  const int*   __restrict__ E,
                                  float4* __restrict__ out,
                                  int npairs, int iters_rt) {
    __shared__ float sC1[5];
    __shared__ float sC2[25];
    __shared__ float sC3[125];
    __shared__ float sTrig[10];

    // ---- block-local decode of E -> canonical coefficient slots ----
    const int tx = threadIdx.x;
    if (tx < 55) {
        int vars[3];
        int nv = 0;
        #pragma unroll
        for (int j = 0; j < 5; j++) {
            int c = E[tx * 5 + j];
            for (int r = 0; r < c; r++) vars[nv++] = j;   // ascending
        }
        float coef = layer[tx];
        if (nv == 1)      sC1[vars[0]] = coef;
        else if (nv == 2) sC2[vars[0] * 5 + vars[1]] = coef;
        else              sC3[(vars[0] * 5 + vars[1]) * 5 + vars[2]] = coef;
    }
    if (tx >= 64 && tx < 74) sTrig[tx - 64] = layer[55 + (tx - 64)];
    __syncthreads();

    // ---- hoist ALL coefficients into registers (broadcast LDS, once) ----
    float c1[5], c2[15], c3[35], ctc[5], cts[5];
    {
        int q2 = 0, q3 = 0;
        #pragma unroll
        for (int i = 0; i < 5; i++) {
            c1[i] = sC1[i];
            ctc[i] = sTrig[i];
            cts[i] = sTrig[5 + i];
            #pragma unroll
            for (int j = i; j < 5; j++) {
                c2[q2++] = sC2[i * 5 + j];
                #pragma unroll
                for (int k = j; k < 5; k++)
                    c3[q3++] = sC3[(i * 5 + j) * 5 + k];
            }
        }
    }
    const float w0 = omegas[0];
    const float w1 = omegas[1];
    const float e0 = ef[0];
    const float e1 = ef[1];

    const int tid = blockIdx.x * NTHR + tx;
    const int pm1 = npairs - 1;
    const int iters = (NITER > 0) ? NITER : iters_rt;

    // Per-thread base pointers: all per-iteration offsets become unroll-time
    // constants relative to these.
    const float4* __restrict__ xp = x + 2 * tid;
    const float2* __restrict__ tp = t2 + tid;
    float4* __restrict__ op = out + tid;

    // ---- parity double-buffer: buf[it & 1] under full unroll -> renaming ----
    Pair buf[2];
    if (NITER > 0) load_pair(xp, tp, 0, buf[0]);
    else {
        int pc = min(tid, pm1) - tid;   // relative clamped offset
        load_pair(xp, tp, pc, buf[0]);
    }

    #pragma unroll
    for (int it = 0; it < iters; it++) {
        const int cur = it & 1;
        const int nxt = cur ^ 1;

        // ---- prefetch iteration it+1 (guard-free except the final load) ----
        if (it + 1 < iters) {
            if (NITER > 0 && it + 2 < iters) {
                // provably in-bounds: raw constant-offset load
                load_pair(xp, tp, (it + 1) * TOTT, buf[nxt]);
            } else {
                int pc = min(tid + (it + 1) * TOTT, pm1) - tid;
                load_pair(xp, tp, pc, buf[nxt]);
            }
        }

        const float* va = buf[cur].a;
        const float* vb = buf[cur].b;

        // ---- trig: issue all 20 MUFUs early ----
        float Ca[5], Sa[5], Cb[5], Sb[5];
        #pragma unroll
        for (int j = 0; j < 5; j++) {
            Ca[j] = __cosf(w0 * va[j]);
            Sa[j] = __sinf(w1 * va[j]);
            Cb[j] = __cosf(w0 * vb[j]);
            Sb[j] = __sinf(w1 * vb[j]);
        }

        // ---- degree-3 Horner: 55 FMAs/row, 5 independent chains per row ----
        float sA, sB;
        {
            float part[5];
            int q2 = 0, q3 = 0;
            #pragma unroll
            for (int i = 0; i < 5; i++) {
                float ui = c1[i];
                #pragma unroll
                for (int j = i; j < 5; j++) {
                    float tij = c2[q2++];
                    #pragma unroll
                    for (int k = j; k < 5; k++)
                        tij = fmaf(va[k], c3[q3++], tij);
                    ui = fmaf(va[j], tij, ui);
                }
                part[i] = va[i] * ui;
            }
            float a01 = fmaf(ctc[0], Ca[0], ctc[1] * Ca[1]);
            float a23 = fmaf(ctc[2], Ca[2], ctc[3] * Ca[3]);
            float b01 = fmaf(cts[0], Sa[0], cts[1] * Sa[1]);
            float b23 = fmaf(cts[2], Sa[2], cts[3] * Sa[3]);
            float a4  = fmaf(ctc[4], Ca[4], cts[4] * Sa[4]);
            sA = (((part[0] + part[1]) + (part[2] + part[3])) + part[4])
                 + (((a01 + a23) + (b01 + b23)) + a4);
        }
        {
            float part[5];
            int q2 = 0, q3 = 0;
            #pragma unroll
            for (int i = 0; i < 5; i++) {
                float ui = c1[i];
                #pragma unroll
                for (int j = i; j < 5; j++) {
                    float tij = c2[q2++];
                    #pragma unroll
                    for (int k = j; k < 5; k++)
                        tij = fmaf(vb[k], c3[q3++], tij);
                    ui = fmaf(vb[j], tij, ui);
                }
                part[i] = vb[i] * ui;
            }
            float a01 = fmaf(ctc[0], Cb[0], ctc[1] * Cb[1]);
            float a23 = fmaf(ctc[2], Cb[2], ctc[3] * Cb[3]);
            float b01 = fmaf(cts[0], Sb[0], cts[1] * Sb[1]);
            float b23 = fmaf(cts[2], Sb[2], cts[3] * Sb[3]);
            float a4  = fmaf(ctc[4], Cb[4], cts[4] * Sb[4]);
            sB = (((part[0] + part[1]) + (part[2] + part[3])) + part[4])
                 + (((a01 + a23) + (b01 + b23)) + a4);
        }

        // ---- one STG.128 per pair; unpredicated on the clean iterations ----
        float4 res = make_float4(sA * e0, sA * e1, sB * e0, sB * e1);
        if (NITER > 0 && it + 1 < iters) {
            op[it * TOTT] = res;                       // provably in-bounds
        } else {
            if (tid + it * TOTT < npairs) op[it * TOTT] = res;
        }
    }
}

extern "C" void kernel_launch(void* const* d_in, const int* in_sizes, int n_in,
                              void* d_out, int out_size) {
    // metadata order: x, t, layer, omegas, ext_filter, E
    const float4* x      = (const float4*)d_in[0];
    const float2* t2     = (const float2*)d_in[1];
    const float*  layer  = (const float*)d_in[2];
    const float*  omegas = (const float*)d_in[3];
    const float*  ef     = (const float*)d_in[4];
    const int*    E      = (const int*)d_in[5];
    float4* out = (float4*)d_out;

    const int n = in_sizes[1];        // N_DATA (element count of t), even
    const int npairs = n >> 1;        // 500000
    const int iters = (npairs + TOTT - 1) / TOTT;

    // Guard-specialized fast path is only valid when iterations 0..iters-2
    // are provably in-bounds for every thread: (iters-1)*TOTT <= npairs.
    if (iters == 7 && (iters - 1) * TOTT <= npairs) {
        ExternalForcesSI_main_kernel<7><<<NBLK, NTHR>>>(
            x, t2, layer, omegas, ef, E, out, npairs, iters);
    } else {
        ExternalForcesSI_main_kernel<0><<<NBLK, NTHR>>>(
            x, t2, layer, omegas, ef, E, out, npairs, iters);
    }
}